// round 1
// baseline (speedup 1.0000x reference)
#include <cuda_runtime.h>
#include <cuda_bf16.h>

#define NN 4096
#define ITERS 12
#define SWEEPS 6

// ---------------- persistent device scratch (static, no runtime alloc) ----------------
__device__ __nv_bfloat16 g_D16[(size_t)NN * NN];   // lamda1 * D_tilda in bf16 (33.5 MB)
__device__ float g_Ddiag[NN];
__device__ float g_qr[NN];        // q + rho
__device__ float g_Minv[NN];      // Jacobi preconditioner
__device__ float g_StS[64 * 64];  // lamda2 * S^T S
__device__ float g_x[NN], g_r[NN], g_z[NN], g_p[NN], g_Ap[NN], g_Az[NN];
__device__ float g_rz[ITERS], g_zAz[ITERS], g_zAp[ITERS], g_pAp[ITERS];

// ---------------- 1) extract diag(D) ----------------
__global__ void diag_kernel(const float* __restrict__ D) {
    int n = blockIdx.x * 1024 + threadIdx.x;
    if (n < NN) g_Ddiag[n] = D[(size_t)n * (NN + 1)];
}

// ---------------- 2) setup: StS, b, Minv, CG state ----------------
__global__ void __launch_bounds__(1024) setup_kernel(
    const float* __restrict__ inp, const float* __restrict__ L,
    const void* __restrict__ maskv, const float* __restrict__ thP,
    const float* __restrict__ l1p, const float* __restrict__ l2p,
    const float* __restrict__ rhop, const float* __restrict__ S)
{
    __shared__ float Ss[64 * 65];
    __shared__ float Ts[64 * 65];
    int t = threadIdx.x;
    float l1 = *l1p, l2 = *l2p, rho = *rhop;

    // detect mask storage: 4-byte words (int32 0/1 or float 0.0/1.0) vs packed bytes
    const unsigned* maskw = (const unsigned*)maskv;
    unsigned wv = maskw[t];  // t<1024: in-bounds for both layouts
    int bad = (wv != 0u && wv != 1u && wv != 0x3F800000u) ? 1 : 0;
    int bytemode = __syncthreads_or(bad);

    for (int i = t; i < 4096; i += 1024) {
        int h = i >> 6, a = i & 63;
        Ss[h * 65 + a] = S[i];
    }
    __syncthreads();
    for (int e = t; e < 4096; e += 1024) {
        int a = e >> 6, b = e & 63;
        float acc = 0.f;
        #pragma unroll 8
        for (int h = 0; h < 64; h++) acc += Ss[h * 65 + a] * Ss[h * 65 + b];
        acc *= l2;
        Ts[a * 65 + b] = acc;
        g_StS[e] = acc;
    }
    __syncthreads();
    const unsigned char* maskb = (const unsigned char*)maskv;
    for (int n = t; n < NN; n += 1024) {
        float qf;
        if (bytemode) qf = (maskb[n] != 0) ? 1.f : 0.f;
        else          qf = (maskw[n] != 0u) ? 1.f : 0.f;
        float qr = qf + rho;
        g_qr[n] = qr;
        int c = n & 63;
        float denom = qr + l1 * g_Ddiag[n] + Ts[c * 65 + c];
        float minv = 1.f / denom;
        g_Minv[n] = minv;
        float b = rho * (L[n] - thP[n]) + (qf != 0.f ? inp[n] : 0.f);
        g_r[n] = b;
        g_z[n] = minv * b;
        g_x[n] = 0.f; g_p[n] = 0.f; g_Ap[n] = 0.f;
    }
    if (t < ITERS) { g_rz[t] = 0.f; g_zAz[t] = 0.f; g_zAp[t] = 0.f; g_pAp[t] = 0.f; }
}

// ---------------- 3) matvec: Az = A z, + fused dots rz, zAz, zAp_old ----------------
// FIRST variant reads fp32 D, scales by lamda1, writes bf16 copy (used thereafter).
template <bool FIRST>
__global__ void __launch_bounds__(256) matvec_kernel(
    const float* __restrict__ Dfp32, const float* __restrict__ l1p, int k)
{
    __shared__ __align__(16) float zs[NN];   // 16 KB
    __shared__ float Ts[64 * 65];            // 16.6 KB (lamda2*StS, padded)
    __shared__ float sred[3];
    int t = threadIdx.x;
    if (t < 3) sred[t] = 0.f;
    for (int i = t; i < NN; i += 256) zs[i] = g_z[i];
    for (int i = t; i < 4096; i += 256) Ts[(i >> 6) * 65 + (i & 63)] = g_StS[i];
    __syncthreads();

    int warp = t >> 5, lane = t & 31;
    int row0 = blockIdx.x * 32 + warp * 4;  // 4 rows per warp
    float acc[4] = {0.f, 0.f, 0.f, 0.f};

    if (FIRST) {
        float l1 = *l1p;
        for (int j = 0; j < 32; j++) {
            int idx = lane + 32 * j;                 // float4 index in row (0..1023)
            float4 z4 = ((const float4*)zs)[idx];
            #pragma unroll
            for (int rr = 0; rr < 4; rr++) {
                const float4* dr = (const float4*)(Dfp32 + (size_t)(row0 + rr) * NN);
                float4 dv = dr[idx];
                dv.x *= l1; dv.y *= l1; dv.z *= l1; dv.w *= l1;
                __nv_bfloat162 b01, b23;
                b01.x = __float2bfloat16_rn(dv.x); b01.y = __float2bfloat16_rn(dv.y);
                b23.x = __float2bfloat16_rn(dv.z); b23.y = __float2bfloat16_rn(dv.w);
                __nv_bfloat162* w2 = (__nv_bfloat162*)(g_D16 + (size_t)(row0 + rr) * NN);
                w2[idx * 2] = b01; w2[idx * 2 + 1] = b23;
                // accumulate with the ROUNDED values so the CG operator is fixed
                float2 f01 = __bfloat1622float2(b01);
                float2 f23 = __bfloat1622float2(b23);
                acc[rr] += f01.x * z4.x + f01.y * z4.y + f23.x * z4.z + f23.y * z4.w;
            }
        }
    } else {
        for (int j = 0; j < 16; j++) {
            int idx = lane + 32 * j;                 // uint4 index (8 bf16) 0..511
            float4 za = ((const float4*)zs)[idx * 2];
            float4 zb = ((const float4*)zs)[idx * 2 + 1];
            #pragma unroll
            for (int rr = 0; rr < 4; rr++) {
                const uint4* dr = (const uint4*)(g_D16 + (size_t)(row0 + rr) * NN);
                uint4 u = dr[idx];
                float2 p0 = __bfloat1622float2(*(__nv_bfloat162*)&u.x);
                float2 p1 = __bfloat1622float2(*(__nv_bfloat162*)&u.y);
                float2 p2 = __bfloat1622float2(*(__nv_bfloat162*)&u.z);
                float2 p3 = __bfloat1622float2(*(__nv_bfloat162*)&u.w);
                acc[rr] += p0.x * za.x + p0.y * za.y + p1.x * za.z + p1.y * za.w
                         + p2.x * zb.x + p2.y * zb.y + p3.x * zb.z + p3.y * zb.w;
            }
        }
    }

    // lamda2 * (Z @ StS) term: row n=(h,u) needs sum_b StS_s[b][u]*z[h*64+b]
    #pragma unroll
    for (int rr = 0; rr < 4; rr++) {
        int row = row0 + rr;
        int h = row >> 6, u = row & 63;
        acc[rr] += Ts[lane * 65 + u] * zs[(h << 6) + lane]
                 + Ts[(lane + 32) * 65 + u] * zs[(h << 6) + lane + 32];
    }
    // butterfly reduce all 4 accumulators
    #pragma unroll
    for (int rr = 0; rr < 4; rr++)
        #pragma unroll
        for (int off = 16; off; off >>= 1)
            acc[rr] += __shfl_xor_sync(0xffffffffu, acc[rr], off);

    float a = (lane == 0) ? acc[0] : (lane == 1) ? acc[1] : (lane == 2) ? acc[2] : acc[3];
    if (lane < 4) {
        int row = row0 + lane;
        float zr = zs[row];
        float Azv = a + g_qr[row] * zr;
        g_Az[row] = Azv;
        atomicAdd(&sred[0], zr * Azv);         // z'Az
        atomicAdd(&sred[1], zr * g_Ap[row]);   // z'Ap_old
        atomicAdd(&sred[2], g_r[row] * zr);    // r'z
    }
    __syncthreads();
    if (t == 0) {
        atomicAdd(&g_zAz[k], sred[0]);
        atomicAdd(&g_zAp[k], sred[1]);
        atomicAdd(&g_rz[k],  sred[2]);
    }
}

// ---------------- 4) CG update (merged PCG recurrences, elementwise) ----------------
__global__ void cg_update(int k) {
    int n = blockIdx.x * blockDim.x + threadIdx.x;
    float rz = g_rz[k];
    float beta = 0.f, pApprev = 0.f;
    if (k > 0) {
        float rzp = g_rz[k - 1];
        beta = (rzp != 0.f) ? rz / rzp : 0.f;
        pApprev = g_pAp[k - 1];
    }
    float pAp = g_zAz[k] + 2.f * beta * g_zAp[k] + beta * beta * pApprev;
    float alpha = (pAp != 0.f) ? rz / pAp : 0.f;
    float zn = g_z[n];
    float pn = zn + beta * g_p[n];
    float Apn = g_Az[n] + beta * g_Ap[n];
    g_p[n] = pn; g_Ap[n] = Apn;
    g_x[n] = g_x[n] + alpha * pn;
    float rn = g_r[n] - alpha * Apn;
    g_r[n] = rn;
    g_z[n] = g_Minv[n] * rn;
    if (n == 0) g_pAp[k] = pAp;
}

// ---------------- 5) SVT via Jacobi eig of B = M^T M  (single block) ----------------
__global__ void __launch_bounds__(1024) svt_kernel(
    const float* __restrict__ thP, const float* __restrict__ vp,
    const float* __restrict__ netap, float* __restrict__ out)
{
    __shared__ float A1[64 * 65];  // M, then V, then M again
    __shared__ float A2[64 * 65];  // B, then W
    __shared__ float sv[64], wv[64];
    __shared__ float smax_s;
    int t = threadIdx.x, warp = t >> 5, lane = t & 31;

    // M = x + th_P
    for (int n = t; n < NN; n += 1024)
        A1[(n >> 6) * 65 + (n & 63)] = g_x[n] + thP[n];
    __syncthreads();
    // B = M^T M
    #pragma unroll
    for (int s4 = 0; s4 < 4; s4++) {
        int e = t + 1024 * s4;
        int i = e >> 6, j = e & 63;
        float acc = 0.f;
        #pragma unroll 8
        for (int kk = 0; kk < 64; kk++) acc += A1[kk * 65 + i] * A1[kk * 65 + j];
        A2[i * 65 + j] = acc;
    }
    __syncthreads();
    // V = I (overwrites M)
    for (int n = t; n < 64 * 65; n += 1024) A1[n] = 0.f;
    __syncthreads();
    if (t < 64) A1[t * 65 + t] = 1.f;
    __syncthreads();

    // parallel cyclic Jacobi: 32 disjoint pairs per round (round-robin tournament)
    for (int sw = 0; sw < SWEEPS; sw++) {
        for (int r = 0; r < 63; r++) {
            int j1 = warp, j2 = 63 - warp;
            int p = (j1 == 0) ? 0 : (1 + ((j1 - 1 + r) % 63));
            int q = 1 + ((j2 - 1 + r) % 63);
            float c = 1.f, s = 0.f;
            if (lane == 0) {
                float app = A2[p * 65 + p], aqq = A2[q * 65 + q], apq = A2[p * 65 + q];
                if (fabsf(apq) > 0.f) {
                    float theta = (aqq - app) / (2.f * apq);
                    float tt = 1.f / (fabsf(theta) + sqrtf(theta * theta + 1.f));
                    if (theta < 0.f) tt = -tt;
                    c = rsqrtf(1.f + tt * tt);
                    s = tt * c;
                }
            }
            c = __shfl_sync(0xffffffffu, c, 0);
            s = __shfl_sync(0xffffffffu, s, 0);
            // row phase: rows p,q (disjoint across warps)
            {
                int k1 = lane, k2 = lane + 32;
                float bp = A2[p * 65 + k1], bq = A2[q * 65 + k1];
                A2[p * 65 + k1] = c * bp - s * bq;
                A2[q * 65 + k1] = s * bp + c * bq;
                bp = A2[p * 65 + k2]; bq = A2[q * 65 + k2];
                A2[p * 65 + k2] = c * bp - s * bq;
                A2[q * 65 + k2] = s * bp + c * bq;
            }
            __syncthreads();
            // col phase (B and V): cols p,q (disjoint across warps)
            {
                int k1 = lane, k2 = lane + 32;
                float bp = A2[k1 * 65 + p], bq = A2[k1 * 65 + q];
                A2[k1 * 65 + p] = c * bp - s * bq;
                A2[k1 * 65 + q] = s * bp + c * bq;
                bp = A2[k2 * 65 + p]; bq = A2[k2 * 65 + q];
                A2[k2 * 65 + p] = c * bp - s * bq;
                A2[k2 * 65 + q] = s * bp + c * bq;
                float vx = A1[k1 * 65 + p], vy = A1[k1 * 65 + q];
                A1[k1 * 65 + p] = c * vx - s * vy;
                A1[k1 * 65 + q] = s * vx + c * vy;
                vx = A1[k2 * 65 + p]; vy = A1[k2 * 65 + q];
                A1[k2 * 65 + p] = c * vx - s * vy;
                A1[k2 * 65 + q] = s * vx + c * vy;
            }
            __syncthreads();
        }
    }

    // singular values, threshold weights
    if (t < 64) sv[t] = sqrtf(fmaxf(A2[t * 65 + t], 0.f));
    __syncthreads();
    if (t < 32) {
        float m = fmaxf(sv[t], sv[t + 32]);
        #pragma unroll
        for (int off = 16; off; off >>= 1) m = fmaxf(m, __shfl_xor_sync(0xffffffffu, m, off));
        if (t == 0) smax_s = m;
    }
    __syncthreads();
    float vscal = *vp;
    float sig = 1.f / (1.f + expf(-vscal));
    float tau_abs = sig * 0.4f * smax_s;
    if (t < 64) {
        float si = sv[t];
        wv[t] = (si > tau_abs) ? (si - tau_abs) / si : 0.f;
    }
    __syncthreads();
    // W = V diag(w) V^T  -> A2
    #pragma unroll
    for (int s4 = 0; s4 < 4; s4++) {
        int e = t + 1024 * s4;
        int i = e >> 6, j = e & 63;
        float acc = 0.f;
        #pragma unroll 8
        for (int kk = 0; kk < 64; kk++) acc += A1[i * 65 + kk] * wv[kk] * A1[j * 65 + kk];
        A2[i * 65 + j] = acc;
    }
    __syncthreads();
    // reload M -> A1
    for (int n = t; n < NN; n += 1024)
        A1[(n >> 6) * 65 + (n & 63)] = g_x[n] + thP[n];
    __syncthreads();
    // Ltmp = M @ W ; Ptmp = th_P + neta*(x - Ltmp)
    float neta = *netap;
    #pragma unroll
    for (int s4 = 0; s4 < 4; s4++) {
        int e = t + 1024 * s4;
        int h = e >> 6, u = e & 63;
        float acc = 0.f;
        #pragma unroll 8
        for (int kk = 0; kk < 64; kk++) acc += A1[h * 65 + kk] * A2[kk * 65 + u];
        out[e] = acc;
        out[NN + e] = thP[e] + neta * (g_x[e] - acc);
    }
}

// ---------------- launch ----------------
extern "C" void kernel_launch(void* const* d_in, const int* in_sizes, int n_in,
                              void* d_out, int out_size) {
    const float* inp  = (const float*)d_in[0];
    const float* L    = (const float*)d_in[1];
    const void*  mask = (const void*)d_in[2];
    const float* D    = (const float*)d_in[3];
    const float* thP  = (const float*)d_in[4];
    const float* v    = (const float*)d_in[5];
    const float* neta = (const float*)d_in[6];
    const float* l1   = (const float*)d_in[7];
    const float* l2   = (const float*)d_in[8];
    const float* rho  = (const float*)d_in[9];
    const float* S    = (const float*)d_in[10];

    diag_kernel<<<4, 1024>>>(D);
    setup_kernel<<<1, 1024>>>(inp, L, mask, thP, l1, l2, rho, S);
    for (int k = 0; k < ITERS; k++) {
        if (k == 0) matvec_kernel<true><<<128, 256>>>(D, l1, k);
        else        matvec_kernel<false><<<128, 256>>>(D, l1, k);
        cg_update<<<16, 256>>>(k);
    }
    svt_kernel<<<1, 1024>>>(thP, v, neta, (float*)d_out);
}